// round 9
// baseline (speedup 1.0000x reference)
#include <cuda_runtime.h>
#include <stdint.h>

#define NCAM 6
#define CCH  128
#define HH   64
#define WW   176
#define HWSZ (HH * WW)          // 11264
#define NQ   (200 * 200 * 16)   // 640000

#define TILE_Q   64
#define QPITCH   132            // floats per query row in smem (mult of 4)
#define TP_PITCH 33             // transpose smem pitch

// 34.6 MB transposed feature scratch: layout (cam, y, x, c), c contiguous.
__device__ float g_feats_t[(size_t)NCAM * HWSZ * CCH];
// bit0: uint8 evidence, bit1: float32 evidence. Monotonic OR; deterministic
// across replays (same inputs -> same bits), so no reset needed.
__device__ int g_valid_flags;

__device__ __forceinline__ void cp_async16(uint32_t smem_addr, const void* gptr) {
    asm volatile("cp.async.cg.shared.global [%0], [%1], 16;"
                 :: "r"(smem_addr), "l"(gptr) : "memory");
}

// Vectorized transpose: (cam, C, HW) -> (cam, HW, C).
// Block (0,0,0) additionally runs the 'valid' dtype detection scan (64KB).
__global__ void transpose_kernel(const float* __restrict__ in,
                                 const uint32_t* __restrict__ valid_words) {
    // ---- folded dtype detection ----
    if (blockIdx.x == 0 && blockIdx.y == 0 && blockIdx.z == 0) {
        int flags = 0;
        const uint4* v4 = (const uint4*)valid_words;
        for (int i = threadIdx.x; i < 4096; i += 256) {
            uint4 u = v4[i];
            uint32_t ws[4] = {u.x, u.y, u.z, u.w};
#pragma unroll
            for (int k = 0; k < 4; k++) {
                uint32_t wd = ws[k];
                if ((wd & 0xFF000000u) == 0x3F000000u) flags |= 2;  // float 1.0f
                if (((wd >> 8)  & 0xFF) == 1u ||
                    ((wd >> 16) & 0xFF) == 1u ||
                    ((wd >> 24) & 0xFF) == 1u) flags |= 1;          // uint8 ones
            }
        }
        flags |= __shfl_xor_sync(0xFFFFFFFF, flags, 16);
        flags |= __shfl_xor_sync(0xFFFFFFFF, flags, 8);
        flags |= __shfl_xor_sync(0xFFFFFFFF, flags, 4);
        flags |= __shfl_xor_sync(0xFFFFFFFF, flags, 2);
        flags |= __shfl_xor_sync(0xFFFFFFFF, flags, 1);
        if ((threadIdx.x & 31) == 0 && flags) atomicOr(&g_valid_flags, flags);
    }

    // ---- transpose: tile = 32 c x 128 p ----
    __shared__ float tile[128 * TP_PITCH];   // [p][c], 16.9 KB
    const int t  = threadIdx.x;
    const int tx = t & 31, ty = t >> 5;
    const int p0  = blockIdx.x * 128;
    const int c0  = blockIdx.y * 32;
    const int cam = blockIdx.z;
    const size_t in_base  = (size_t)cam * CCH * HWSZ;
    const size_t out_base = (size_t)cam * HWSZ * CCH;

#pragma unroll
    for (int k = 0; k < 4; k++) {
        const int cl = ty + 8 * k;           // 0..31
        float4 v = *(const float4*)(in + in_base + (size_t)(c0 + cl) * HWSZ
                                    + p0 + 4 * tx);
        tile[(4 * tx + 0) * TP_PITCH + cl] = v.x;
        tile[(4 * tx + 1) * TP_PITCH + cl] = v.y;
        tile[(4 * tx + 2) * TP_PITCH + cl] = v.z;
        tile[(4 * tx + 3) * TP_PITCH + cl] = v.w;
    }
    __syncthreads();
#pragma unroll
    for (int k = 0; k < 4; k++) {
        const int i  = t + 256 * k;
        const int c4 = i & 7, p = i >> 3;
        float4 v;
        v.x = tile[p * TP_PITCH + 4 * c4 + 0];
        v.y = tile[p * TP_PITCH + 4 * c4 + 1];
        v.z = tile[p * TP_PITCH + 4 * c4 + 2];
        v.w = tile[p * TP_PITCH + 4 * c4 + 3];
        *(float4*)(g_feats_t + out_base + (size_t)(p0 + p) * CCH + c0 + 4 * c4) = v;
    }
}

// Block = 512 threads handles TILE_Q=64 queries -> 4 blocks/SM = 100% occ.
// Phase A: 8 lanes per query (6 cam roles), 3-round shfl-max -> sel.
// Phase B: cp.async 16B/lane, 4 query rows per warp, no register landing.
// Phase C: conflict-free LDS.128 of channel quads, scale applied here,
//          4x coalesced 128B streaming stores per iteration.
__global__ void __launch_bounds__(512, 4)
gather_kernel(const float* __restrict__ points,
              const void* __restrict__ valid,
              float* __restrict__ out) {
    __shared__ float s_feat[TILE_Q * QPITCH];   // 33.8 KB
    __shared__ float s_scale[TILE_Q];

    const int q0   = blockIdx.x * TILE_Q;
    const int tid  = threadIdx.x;
    const int lane = tid & 31;
    const int w    = tid >> 5;                // 0..15

    // ---- Phase A: 8 lanes per query ----
    const int grp = lane >> 3;            // query-in-warp 0..3
    const int r   = lane & 7;             // cam role (r<6 active)
    const int ql0 = w * 4 + grp;          // query-in-tile 0..63
    const int q   = q0 + ql0;

    const int flags = g_valid_flags;
    const int mode = (flags & 2) ? 2 : ((flags & 1) ? 1 : 0);

    int sel = -1;
    if (r < NCAM) {
        if (mode == 0) {
            const int* v = (const int*)valid;
            if (v[(size_t)r * NQ + q] != 0) sel = r;
        } else if (mode == 1) {
            const uint8_t* v = (const uint8_t*)valid;
            if (v[(size_t)r * NQ + q] != 0) sel = r;
        } else {
            const float* v = (const float*)valid;
            if (v[(size_t)r * NQ + q] != 0.0f) sel = r;
        }
    }
    sel = max(sel, __shfl_xor_sync(0xFFFFFFFFu, sel, 1));
    sel = max(sel, __shfl_xor_sync(0xFFFFFFFFu, sel, 2));
    sel = max(sel, __shfl_xor_sync(0xFFFFFFFFu, sel, 4));

    const float scale = (sel >= 0) ? 1.0f : 0.0f;   // any_valid
    const int cam = max(sel, 0);                     // matches reference

    const float2 pt = ((const float2*)points)[(size_t)cam * NQ + q];
    int x = __float2int_rn(pt.x);   // round-half-to-even == jnp.round
    int y = __float2int_rn(pt.y);
    x = max(0, min(WW - 1, x));
    y = max(0, min(HH - 1, y));
    const int base = ((cam * HH + y) * WW + x) * CCH;

    if (r == 0) s_scale[ql0] = scale;

    // ---- Phase B: async row fetches (4 rows per warp) ----
    const uint32_t s_addr =
        (uint32_t)__cvta_generic_to_shared(s_feat) + 16 * lane;
#pragma unroll
    for (int j = 0; j < 4; j++) {
        const int bj = __shfl_sync(0xFFFFFFFFu, base, j * 8);
        cp_async16(s_addr + (w * 4 + j) * (QPITCH * 4),
                   g_feats_t + bj + 4 * lane);
    }
    asm volatile("cp.async.commit_group;");
    asm volatile("cp.async.wait_all;" ::: "memory");
    __syncthreads();

    // ---- Phase C: scaled coalesced output stores ----
#pragma unroll
    for (int i = 0; i < 4; i++) {
        const int it = w + 16 * i;           // 0..63
        const int c4 = it >> 1;              // channel quad 0..31
        const int qh = it & 1;               // query half
        const int ql = qh * 32 + lane;
        const float s = s_scale[ql];
        float4 f = *(const float4*)(s_feat + ql * QPITCH + 4 * c4);
        const size_t qq = (size_t)(q0 + ql);
        __stcs(&out[(size_t)(4 * c4 + 0) * NQ + qq], f.x * s);
        __stcs(&out[(size_t)(4 * c4 + 1) * NQ + qq], f.y * s);
        __stcs(&out[(size_t)(4 * c4 + 2) * NQ + qq], f.z * s);
        __stcs(&out[(size_t)(4 * c4 + 3) * NQ + qq], f.w * s);
    }
}

extern "C" void kernel_launch(void* const* d_in, const int* in_sizes, int n_in,
                              void* d_out, int out_size) {
    const float* img_feats = (const float*)d_in[0];
    const float* points    = (const float*)d_in[1];
    const void*  valid     = d_in[2];
    float* out = (float*)d_out;

    dim3 tb(256);
    dim3 tg(HWSZ / 128, CCH / 32, NCAM);
    transpose_kernel<<<tg, tb>>>(img_feats, (const uint32_t*)valid);

    gather_kernel<<<NQ / TILE_Q, 512>>>(points, valid, out);
}

// round 11
// speedup vs baseline: 1.1871x; 1.1871x over previous
#include <cuda_runtime.h>
#include <stdint.h>

#define NCAM 6
#define CCH  128
#define HH   64
#define WW   176
#define HWSZ (HH * WW)          // 11264
#define NQ   (200 * 200 * 16)   // 640000

#define TILE_Q   32             // queries per pipeline stage
#define NT       4              // tiles per block
#define QPITCH   132            // floats per query row in smem
#define STAGE_F  (TILE_Q * QPITCH)   // floats per stage (4224)
#define TP_PITCH 33             // transpose smem pitch

// 34.6 MB transposed feature scratch: layout (cam, y, x, c), c contiguous.
__device__ float g_feats_t[(size_t)NCAM * HWSZ * CCH];
// bit0: uint8 evidence, bit1: float32 evidence. Monotonic OR; deterministic.
__device__ int g_valid_flags;

__device__ __forceinline__ void cp_async16(uint32_t smem_addr, const void* gptr) {
    asm volatile("cp.async.cg.shared.global [%0], [%1], 16;"
                 :: "r"(smem_addr), "l"(gptr) : "memory");
}
__device__ __forceinline__ void cp_commit() {
    asm volatile("cp.async.commit_group;");
}
template <int N>
__device__ __forceinline__ void cp_wait() {
    asm volatile("cp.async.wait_group %0;" :: "n"(N) : "memory");
}

// Vectorized transpose: (cam, C, HW) -> (cam, HW, C).
// Block (0,0,0) additionally runs the 'valid' dtype detection scan (64KB).
__global__ void transpose_kernel(const float* __restrict__ in,
                                 const uint32_t* __restrict__ valid_words) {
    if (blockIdx.x == 0 && blockIdx.y == 0 && blockIdx.z == 0) {
        int flags = 0;
        const uint4* v4 = (const uint4*)valid_words;
        for (int i = threadIdx.x; i < 4096; i += 256) {
            uint4 u = v4[i];
            uint32_t ws[4] = {u.x, u.y, u.z, u.w};
#pragma unroll
            for (int k = 0; k < 4; k++) {
                uint32_t wd = ws[k];
                if ((wd & 0xFF000000u) == 0x3F000000u) flags |= 2;  // float 1.0f
                if (((wd >> 8)  & 0xFF) == 1u ||
                    ((wd >> 16) & 0xFF) == 1u ||
                    ((wd >> 24) & 0xFF) == 1u) flags |= 1;          // uint8 ones
            }
        }
        flags |= __shfl_xor_sync(0xFFFFFFFF, flags, 16);
        flags |= __shfl_xor_sync(0xFFFFFFFF, flags, 8);
        flags |= __shfl_xor_sync(0xFFFFFFFF, flags, 4);
        flags |= __shfl_xor_sync(0xFFFFFFFF, flags, 2);
        flags |= __shfl_xor_sync(0xFFFFFFFF, flags, 1);
        if ((threadIdx.x & 31) == 0 && flags) atomicOr(&g_valid_flags, flags);
    }

    __shared__ float tile[128 * TP_PITCH];   // [p][c], 16.9 KB
    const int t  = threadIdx.x;
    const int tx = t & 31, ty = t >> 5;
    const int p0  = blockIdx.x * 128;
    const int c0  = blockIdx.y * 32;
    const int cam = blockIdx.z;
    const size_t in_base  = (size_t)cam * CCH * HWSZ;
    const size_t out_base = (size_t)cam * HWSZ * CCH;

#pragma unroll
    for (int k = 0; k < 4; k++) {
        const int cl = ty + 8 * k;
        float4 v = *(const float4*)(in + in_base + (size_t)(c0 + cl) * HWSZ
                                    + p0 + 4 * tx);
        tile[(4 * tx + 0) * TP_PITCH + cl] = v.x;
        tile[(4 * tx + 1) * TP_PITCH + cl] = v.y;
        tile[(4 * tx + 2) * TP_PITCH + cl] = v.z;
        tile[(4 * tx + 3) * TP_PITCH + cl] = v.w;
    }
    __syncthreads();
#pragma unroll
    for (int k = 0; k < 4; k++) {
        const int i  = t + 256 * k;
        const int c4 = i & 7, p = i >> 3;
        float4 v;
        v.x = tile[p * TP_PITCH + 4 * c4 + 0];
        v.y = tile[p * TP_PITCH + 4 * c4 + 1];
        v.z = tile[p * TP_PITCH + 4 * c4 + 2];
        v.w = tile[p * TP_PITCH + 4 * c4 + 3];
        *(float4*)(g_feats_t + out_base + (size_t)(p0 + p) * CCH + c0 + 4 * c4) = v;
    }
}

// Pipelined gather. Block = 256 threads processes NT=4 tiles of 32 queries
// with a 2-stage double buffer. Steady state: Phase A + cp.async issue for
// tile i+1 overlap the in-flight copies of tile i; wait_group(1) then finds
// tile i's data already resident -> no exposed copy latency.
struct AResult { int base; float scale; };

template <int MODE>
__device__ __forceinline__ AResult phase_a(const float* __restrict__ points,
                                           const void* __restrict__ valid,
                                           int q, int r) {
    int sel = -1;
    if (r < NCAM) {
        if (MODE == 0) {
            const int* v = (const int*)valid;
            if (v[(size_t)r * NQ + q] != 0) sel = r;
        } else if (MODE == 1) {
            const uint8_t* v = (const uint8_t*)valid;
            if (v[(size_t)r * NQ + q] != 0) sel = r;
        } else {
            const float* v = (const float*)valid;
            if (v[(size_t)r * NQ + q] != 0.0f) sel = r;
        }
    }
    sel = max(sel, __shfl_xor_sync(0xFFFFFFFFu, sel, 1));
    sel = max(sel, __shfl_xor_sync(0xFFFFFFFFu, sel, 2));
    sel = max(sel, __shfl_xor_sync(0xFFFFFFFFu, sel, 4));

    AResult res;
    res.scale = (sel >= 0) ? 1.0f : 0.0f;    // any_valid
    const int cam = max(sel, 0);             // matches reference

    const float2 pt = ((const float2*)points)[(size_t)cam * NQ + q];
    int x = __float2int_rn(pt.x);   // round-half-to-even == jnp.round
    int y = __float2int_rn(pt.y);
    x = max(0, min(WW - 1, x));
    y = max(0, min(HH - 1, y));
    res.base = ((cam * HH + y) * WW + x) * CCH;
    return res;
}

template <int MODE>
__device__ __forceinline__ void gather_body(const float* __restrict__ points,
                                            const void* __restrict__ valid,
                                            float* __restrict__ out,
                                            float* s_feat, float* s_scale) {
    const int q0   = blockIdx.x * (NT * TILE_Q);
    const int tid  = threadIdx.x;
    const int lane = tid & 31;
    const int w    = tid >> 5;            // 0..7

    const int grp = lane >> 3;            // query-in-warp 0..3
    const int r   = lane & 7;             // cam role
    const int qw  = w * 4 + grp;          // query-in-tile 0..31

    const uint32_t s_base = (uint32_t)__cvta_generic_to_shared(s_feat);

    // ---- prologue: tile 0 ----
    {
        AResult a = phase_a<MODE>(points, valid, q0 + qw, r);
        if (r == 0) s_scale[qw] = a.scale;
#pragma unroll
        for (int j = 0; j < 4; j++) {
            const int bj = __shfl_sync(0xFFFFFFFFu, a.base, j * 8);
            cp_async16(s_base + ((w * 4 + j) * QPITCH * 4 + 16 * lane),
                       g_feats_t + bj + 4 * lane);
        }
        cp_commit();
    }

#pragma unroll
    for (int i = 0; i < NT; i++) {
        const int cur = i & 1;
        // ---- issue next tile (Phase A + B) before waiting on current ----
        if (i + 1 < NT) {
            const int nxt = (i + 1) & 1;
            AResult a = phase_a<MODE>(points, valid,
                                      q0 + (i + 1) * TILE_Q + qw, r);
            if (r == 0) s_scale[nxt * TILE_Q + qw] = a.scale;
#pragma unroll
            for (int j = 0; j < 4; j++) {
                const int bj = __shfl_sync(0xFFFFFFFFu, a.base, j * 8);
                cp_async16(s_base + (nxt * STAGE_F + (w * 4 + j) * QPITCH) * 4
                               + 16 * lane,
                           g_feats_t + bj + 4 * lane);
            }
            cp_commit();
            cp_wait<1>();
        } else {
            cp_wait<0>();
        }
        __syncthreads();

        // ---- Phase C for tile i: coalesced scaled stores ----
        const float* buf = s_feat + cur * STAGE_F;
        const size_t qq = (size_t)(q0 + i * TILE_Q + lane);
        const float s = s_scale[cur * TILE_Q + lane];
#pragma unroll
        for (int k = 0; k < 4; k++) {
            const int c4 = w * 4 + k;        // channel quad 0..31
            float4 f = *(const float4*)(buf + lane * QPITCH + 4 * c4);
            __stcs(&out[(size_t)(4 * c4 + 0) * NQ + qq], f.x * s);
            __stcs(&out[(size_t)(4 * c4 + 1) * NQ + qq], f.y * s);
            __stcs(&out[(size_t)(4 * c4 + 2) * NQ + qq], f.z * s);
            __stcs(&out[(size_t)(4 * c4 + 3) * NQ + qq], f.w * s);
        }
        __syncthreads();   // buffer reuse fence for next cp.async round
    }
}

__global__ void __launch_bounds__(256, 6)
gather_kernel(const float* __restrict__ points,
              const void* __restrict__ valid,
              float* __restrict__ out) {
    __shared__ float s_feat[2 * STAGE_F];    // 33.8 KB
    __shared__ float s_scale[2 * TILE_Q];

    const int flags = g_valid_flags;
    if (flags & 2)      gather_body<2>(points, valid, out, s_feat, s_scale);
    else if (flags & 1) gather_body<1>(points, valid, out, s_feat, s_scale);
    else                gather_body<0>(points, valid, out, s_feat, s_scale);
}

extern "C" void kernel_launch(void* const* d_in, const int* in_sizes, int n_in,
                              void* d_out, int out_size) {
    const float* img_feats = (const float*)d_in[0];
    const float* points    = (const float*)d_in[1];
    const void*  valid     = d_in[2];
    float* out = (float*)d_out;

    dim3 tb(256);
    dim3 tg(HWSZ / 128, CCH / 32, NCAM);
    transpose_kernel<<<tg, tb>>>(img_feats, (const uint32_t*)valid);

    gather_kernel<<<NQ / (NT * TILE_Q), 256>>>(points, valid, out);
}

// round 12
// speedup vs baseline: 1.1942x; 1.0060x over previous
#include <cuda_runtime.h>
#include <stdint.h>

#define NCAM 6
#define CCH  128
#define HH   64
#define WW   176
#define HWSZ (HH * WW)          // 11264
#define NQ   (200 * 200 * 16)   // 640000

#define TILE_Q   32             // queries per pipeline stage
#define NT       8              // tiles per block
#define QPITCH   132            // floats per query row in smem
#define STAGE_F  (TILE_Q * QPITCH)   // floats per stage (4224)
#define TP_PITCH 33             // transpose smem pitch

// 34.6 MB transposed feature scratch: layout (cam, y, x, c), c contiguous.
__device__ float g_feats_t[(size_t)NCAM * HWSZ * CCH];
// bit0: uint8 evidence, bit1: float32 evidence. Monotonic OR; deterministic.
__device__ int g_valid_flags;

__device__ __forceinline__ void cp_async16(uint32_t smem_addr, const void* gptr) {
    asm volatile("cp.async.cg.shared.global [%0], [%1], 16;"
                 :: "r"(smem_addr), "l"(gptr) : "memory");
}
__device__ __forceinline__ void cp_commit() {
    asm volatile("cp.async.commit_group;");
}
template <int N>
__device__ __forceinline__ void cp_wait() {
    asm volatile("cp.async.wait_group %0;" :: "n"(N) : "memory");
}

// Vectorized transpose: (cam, C, HW) -> (cam, HW, C).
// Block (0,0,0) additionally runs the 'valid' dtype detection scan (64KB).
__global__ void transpose_kernel(const float* __restrict__ in,
                                 const uint32_t* __restrict__ valid_words) {
    if (blockIdx.x == 0 && blockIdx.y == 0 && blockIdx.z == 0) {
        int flags = 0;
        const uint4* v4 = (const uint4*)valid_words;
        for (int i = threadIdx.x; i < 4096; i += 256) {
            uint4 u = v4[i];
            uint32_t ws[4] = {u.x, u.y, u.z, u.w};
#pragma unroll
            for (int k = 0; k < 4; k++) {
                uint32_t wd = ws[k];
                if ((wd & 0xFF000000u) == 0x3F000000u) flags |= 2;  // float 1.0f
                if (((wd >> 8)  & 0xFF) == 1u ||
                    ((wd >> 16) & 0xFF) == 1u ||
                    ((wd >> 24) & 0xFF) == 1u) flags |= 1;          // uint8 ones
            }
        }
        flags |= __shfl_xor_sync(0xFFFFFFFF, flags, 16);
        flags |= __shfl_xor_sync(0xFFFFFFFF, flags, 8);
        flags |= __shfl_xor_sync(0xFFFFFFFF, flags, 4);
        flags |= __shfl_xor_sync(0xFFFFFFFF, flags, 2);
        flags |= __shfl_xor_sync(0xFFFFFFFF, flags, 1);
        if ((threadIdx.x & 31) == 0 && flags) atomicOr(&g_valid_flags, flags);
    }

    __shared__ float tile[128 * TP_PITCH];   // [p][c], 16.9 KB
    const int t  = threadIdx.x;
    const int tx = t & 31, ty = t >> 5;
    const int p0  = blockIdx.x * 128;
    const int c0  = blockIdx.y * 32;
    const int cam = blockIdx.z;
    const size_t in_base  = (size_t)cam * CCH * HWSZ;
    const size_t out_base = (size_t)cam * HWSZ * CCH;

#pragma unroll
    for (int k = 0; k < 4; k++) {
        const int cl = ty + 8 * k;
        float4 v = *(const float4*)(in + in_base + (size_t)(c0 + cl) * HWSZ
                                    + p0 + 4 * tx);
        tile[(4 * tx + 0) * TP_PITCH + cl] = v.x;
        tile[(4 * tx + 1) * TP_PITCH + cl] = v.y;
        tile[(4 * tx + 2) * TP_PITCH + cl] = v.z;
        tile[(4 * tx + 3) * TP_PITCH + cl] = v.w;
    }
    __syncthreads();
#pragma unroll
    for (int k = 0; k < 4; k++) {
        const int i  = t + 256 * k;
        const int c4 = i & 7, p = i >> 3;
        float4 v;
        v.x = tile[p * TP_PITCH + 4 * c4 + 0];
        v.y = tile[p * TP_PITCH + 4 * c4 + 1];
        v.z = tile[p * TP_PITCH + 4 * c4 + 2];
        v.w = tile[p * TP_PITCH + 4 * c4 + 3];
        *(float4*)(g_feats_t + out_base + (size_t)(p0 + p) * CCH + c0 + 4 * c4) = v;
    }
}

// Phase A with SPECULATIVE parallel loads: lane role r loads valid[r][q] AND
// points[r][q] concurrently (one round-trip instead of valid->cam->points).
// Each lane computes its own candidate base; the consumer shfl-selects the
// winning camera's base per query.
template <int MODE>
__device__ __forceinline__ void phase_a(const float* __restrict__ points,
                                        const void* __restrict__ valid,
                                        int q, int r,
                                        int& baseCand, int& cam, float& scale) {
    int hit = 0;
    float2 pt = make_float2(0.0f, 0.0f);
    if (r < NCAM) {
        if (MODE == 0) {
            hit = (((const int*)valid)[(size_t)r * NQ + q] != 0);
        } else if (MODE == 1) {
            hit = (((const uint8_t*)valid)[(size_t)r * NQ + q] != 0);
        } else {
            hit = (((const float*)valid)[(size_t)r * NQ + q] != 0.0f);
        }
        pt = ((const float2*)points)[(size_t)r * NQ + q];
    }
    int sel = hit ? r : -1;
    sel = max(sel, __shfl_xor_sync(0xFFFFFFFFu, sel, 1));
    sel = max(sel, __shfl_xor_sync(0xFFFFFFFFu, sel, 2));
    sel = max(sel, __shfl_xor_sync(0xFFFFFFFFu, sel, 4));

    scale = (sel >= 0) ? 1.0f : 0.0f;    // any_valid
    cam = max(sel, 0);                   // matches reference

    int x = __float2int_rn(pt.x);   // round-half-to-even == jnp.round
    int y = __float2int_rn(pt.y);
    x = max(0, min(WW - 1, x));
    y = max(0, min(HH - 1, y));
    baseCand = ((r * HH + y) * WW + x) * CCH;   // meaningful on lane r==cam
}

template <int MODE>
__device__ __forceinline__ void issue_tile(const float* __restrict__ points,
                                           const void* __restrict__ valid,
                                           int q0t, int r, int grp, int w,
                                           uint32_t s_stage, float* s_scale) {
    int baseCand, cam; float scale;
    phase_a<MODE>(points, valid, q0t + w * 4 + grp, r, baseCand, cam, scale);
    if (r == 0) s_scale[w * 4 + grp] = scale;

    const int lane = (threadIdx.x & 31);
#pragma unroll
    for (int j = 0; j < 4; j++) {
        const int camj = __shfl_sync(0xFFFFFFFFu, cam, j * 8);
        const int bj   = __shfl_sync(0xFFFFFFFFu, baseCand, j * 8 + camj);
        cp_async16(s_stage + ((w * 4 + j) * QPITCH) * 4 + 16 * lane,
                   g_feats_t + bj + 4 * lane);
    }
    cp_commit();
}

template <int MODE>
__device__ __forceinline__ void gather_body(const float* __restrict__ points,
                                            const void* __restrict__ valid,
                                            float* __restrict__ out,
                                            float* s_feat, float* s_scale) {
    const int q0   = blockIdx.x * (NT * TILE_Q);
    const int tid  = threadIdx.x;
    const int lane = tid & 31;
    const int w    = tid >> 5;            // 0..7
    const int grp  = lane >> 3;           // query-in-warp 0..3
    const int r    = lane & 7;            // cam role

    const uint32_t s_base = (uint32_t)__cvta_generic_to_shared(s_feat);

    // ---- prologue: tile 0 ----
    issue_tile<MODE>(points, valid, q0, r, grp, w, s_base, s_scale);

#pragma unroll
    for (int i = 0; i < NT; i++) {
        const int cur = i & 1;
        if (i + 1 < NT) {
            const int nxt = (i + 1) & 1;
            issue_tile<MODE>(points, valid, q0 + (i + 1) * TILE_Q, r, grp, w,
                             s_base + nxt * STAGE_F * 4,
                             s_scale + nxt * TILE_Q);
            cp_wait<1>();
        } else {
            cp_wait<0>();
        }
        __syncthreads();

        // ---- Phase C for tile i: coalesced scaled stores ----
        const float* buf = s_feat + cur * STAGE_F;
        const size_t qq = (size_t)(q0 + i * TILE_Q + lane);
        const float s = s_scale[cur * TILE_Q + lane];
#pragma unroll
        for (int k = 0; k < 4; k++) {
            const int c4 = w * 4 + k;        // channel quad 0..31
            float4 f = *(const float4*)(buf + lane * QPITCH + 4 * c4);
            __stcs(&out[(size_t)(4 * c4 + 0) * NQ + qq], f.x * s);
            __stcs(&out[(size_t)(4 * c4 + 1) * NQ + qq], f.y * s);
            __stcs(&out[(size_t)(4 * c4 + 2) * NQ + qq], f.z * s);
            __stcs(&out[(size_t)(4 * c4 + 3) * NQ + qq], f.w * s);
        }
        __syncthreads();   // buffer reuse fence for next cp.async round
    }
}

__global__ void __launch_bounds__(256, 6)
gather_kernel(const float* __restrict__ points,
              const void* __restrict__ valid,
              float* __restrict__ out) {
    __shared__ float s_feat[2 * STAGE_F];    // 33.8 KB
    __shared__ float s_scale[2 * TILE_Q];

    const int flags = g_valid_flags;
    if (flags & 2)      gather_body<2>(points, valid, out, s_feat, s_scale);
    else if (flags & 1) gather_body<1>(points, valid, out, s_feat, s_scale);
    else                gather_body<0>(points, valid, out, s_feat, s_scale);
}

extern "C" void kernel_launch(void* const* d_in, const int* in_sizes, int n_in,
                              void* d_out, int out_size) {
    const float* img_feats = (const float*)d_in[0];
    const float* points    = (const float*)d_in[1];
    const void*  valid     = d_in[2];
    float* out = (float*)d_out;

    dim3 tb(256);
    dim3 tg(HWSZ / 128, CCH / 32, NCAM);
    transpose_kernel<<<tg, tb>>>(img_feats, (const uint32_t*)valid);

    gather_kernel<<<NQ / (NT * TILE_Q), 256>>>(points, valid, out);
}